// round 2
// baseline (speedup 1.0000x reference)
#include <cuda_runtime.h>

// Laplacian pyramid, 5 levels, input (16,3,1024,1024) fp32, edge-clamp padding.
// Fused per-level kernel: reduce + laplacian from one SMEM-resident fine tile.
// Output = concat(lpyr0, lpyr1, lpyr2, lpyr3, g4).

#define NIMG 48  // 16 * 3

// Scratch for intermediate gaussian levels (allocation-free per harness rules).
__device__ float g_g1[NIMG * 512 * 512];
__device__ float g_g2[NIMG * 256 * 256];
__device__ float g_g3[NIMG * 128 * 128];

// ---------------------------------------------------------------------------
// Fused kernel for one level:
//   coarse_out = pyr_reduce(fine)           (5x5 binomial, stride 2, edge clamp)
//   lap_out    = fine - pyr_expand(coarse)  (polyphase 3x3/2x2 taps, edge clamp)
//
// Tile: 64x128 fine pixels (32x64 coarse). SMEM holds the fine tile with a
// 7-px halo (4 left/top, 3 right/bottom) and the coarse tile with 1 halo.
// Edge clamping is baked into the halo load: sf[r][c] = fine[clamp(y),clamp(x)],
// so every later read of a "virtual" out-of-range coordinate automatically
// returns the edge-replicated value, matching jnp.pad(..., 'edge').
// ---------------------------------------------------------------------------
template <int Hc, int Wc>
__global__ __launch_bounds__(256) void fused_level_kernel(
    const float* __restrict__ fine,
    float* __restrict__ coarse_out,
    float* __restrict__ lap_out)
{
    constexpr int H = 2 * Hc, W = 2 * Wc;
    constexpr int TCY = 32, TCX = 64;     // coarse tile
    constexpr int SFY = 2 * TCY + 7;      // 71 fine rows  (halo: -4 .. +66)
    constexpr int SFX = 2 * TCX + 7;      // 135 fine cols
    constexpr int SCY = TCY + 2;          // 34 coarse rows (halo 1)
    constexpr int SCX = TCX + 2;          // 66 coarse cols

    __shared__ float sf[SFY][SFX + 1];    // stride 136
    __shared__ float sc[SCY][SCX + 2];    // stride 68

    const int tid = threadIdx.x;
    const int img = blockIdx.z;
    const int c0y = blockIdx.y * TCY;
    const int c0x = blockIdx.x * TCX;
    const int f0y = 2 * c0y, f0x = 2 * c0x;

    const float* fp = fine + (size_t)img * H * W;

    // ---- load fine tile + halo (origin f0y-4, f0x-4), edge clamp ----
    {
        const int ty = tid >> 7;          // 0..1
        const int tx = tid & 127;         // 0..127
        for (int r = ty; r < SFY; r += 2) {
            int gy = f0y - 4 + r;
            gy = gy < 0 ? 0 : (gy >= H ? H - 1 : gy);
            const float* row = fp + (size_t)gy * W;
#pragma unroll
            for (int c = tx; c < SFX; c += 128) {
                int gx = f0x - 4 + c;
                gx = gx < 0 ? 0 : (gx >= W ? W - 1 : gx);
                sf[r][c] = row[gx];
            }
        }
    }
    __syncthreads();

    // ---- compute coarse tile + 1 halo; write interior coarse to global ----
    {
        float* cop = coarse_out + (size_t)img * Hc * Wc;
        const int ty = tid >> 6;          // 0..3
        const int tx = tid & 63;          // 0..63
        for (int cr = ty; cr < SCY; cr += 4) {
            int ci = c0y - 1 + cr;
            int cic = ci < 0 ? 0 : (ci >= Hc ? Hc - 1 : ci);
            int ry = 2 * cic - f0y + 4;   // in [0, SFY-1-? ] by construction
#pragma unroll
            for (int cc = tx; cc < SCX; cc += 64) {
                int cj = c0x - 1 + cc;
                int cjc = cj < 0 ? 0 : (cj >= Wc ? Wc - 1 : cj);
                int rx = 2 * cjc - f0x + 4;
                float acc = 0.0f;
                const float hv[5] = {0.0625f, 0.25f, 0.375f, 0.25f, 0.0625f};
#pragma unroll
                for (int a = 0; a < 5; a++) {
                    const float* row = &sf[ry + a - 2][rx - 2];
                    float rs = fmaf(0.0625f, row[0],
                               fmaf(0.25f,   row[1],
                               fmaf(0.375f,  row[2],
                               fmaf(0.25f,   row[3],
                                    0.0625f * row[4]))));
                    acc = fmaf(hv[a], rs, acc);
                }
                sc[cr][cc] = acc;
                if (cr >= 1 && cr <= TCY && cc >= 1 && cc <= TCX)
                    cop[(size_t)(c0y + cr - 1) * Wc + (c0x + cc - 1)] = acc;
            }
        }
    }
    __syncthreads();

    // ---- laplacian: each iteration handles one coarse pos -> 2x2 fine px ----
    {
        float* lop = lap_out + (size_t)img * H * W;
        const int ty = tid >> 6;          // 0..3
        const int jl = tid & 63;          // exactly TCX columns
        for (int il = ty; il < TCY; il += 4) {
            // coarse 3x3 around inner position (il, jl) -> sc[il..il+2][jl..jl+2]
            float c00 = sc[il][jl],     c01 = sc[il][jl + 1],     c02 = sc[il][jl + 2];
            float c10 = sc[il + 1][jl], c11 = sc[il + 1][jl + 1], c12 = sc[il + 1][jl + 2];
            float c20 = sc[il + 2][jl], c21 = sc[il + 2][jl + 1], c22 = sc[il + 2][jl + 2];

            float rowE0 = fmaf(0.125f, c00, fmaf(0.75f, c01, 0.125f * c02));
            float rowE1 = fmaf(0.125f, c10, fmaf(0.75f, c11, 0.125f * c12));
            float rowE2 = fmaf(0.125f, c20, fmaf(0.75f, c21, 0.125f * c22));
            float rowO0 = 0.5f * (c01 + c02);
            float rowO1 = 0.5f * (c11 + c12);
            float rowO2 = 0.5f * (c21 + c22);

            float o00 = fmaf(0.125f, rowE0, fmaf(0.75f, rowE1, 0.125f * rowE2));
            float o01 = fmaf(0.125f, rowO0, fmaf(0.75f, rowO1, 0.125f * rowO2));
            float o10 = 0.5f * (rowE1 + rowE2);
            float o11 = 0.5f * (rowO1 + rowO2);

            int ry = 2 * il + 4, rx = 2 * jl + 4;
            float f00 = sf[ry][rx],     f01 = sf[ry][rx + 1];
            float f10 = sf[ry + 1][rx], f11 = sf[ry + 1][rx + 1];

            int gy = f0y + 2 * il, gx = f0x + 2 * jl;
            float2 t = make_float2(f00 - o00, f01 - o01);
            float2 b = make_float2(f10 - o10, f11 - o11);
            *(float2*)&lop[(size_t)gy * W + gx] = t;
            *(float2*)&lop[(size_t)(gy + 1) * W + gx] = b;
        }
    }
}

// ---------------------------------------------------------------------------
// Launch
// ---------------------------------------------------------------------------
extern "C" void kernel_launch(void* const* d_in, const int* in_sizes, int n_in,
                              void* d_out, int out_size) {
    const float* im = (const float*)d_in[0];
    float* out = (float*)d_out;

    float* g1;
    float* g2;
    float* g3;
    cudaGetSymbolAddress((void**)&g1, g_g1);
    cudaGetSymbolAddress((void**)&g2, g_g2);
    cudaGetSymbolAddress((void**)&g3, g_g3);

    // output section offsets (elements)
    const long long off0 = 0;
    const long long off1 = off0 + (long long)NIMG * 1024 * 1024;
    const long long off2 = off1 + (long long)NIMG * 512 * 512;
    const long long off3 = off2 + (long long)NIMG * 256 * 256;
    const long long off4 = off3 + (long long)NIMG * 128 * 128;

    // level l: fine = g_l, writes g_{l+1} and lap_l
    {
        dim3 grid(512 / 64, 512 / 32, NIMG);  // coarse 512x512
        fused_level_kernel<512, 512><<<grid, 256>>>(im, g1, out + off0);
    }
    {
        dim3 grid(256 / 64, 256 / 32, NIMG);  // coarse 256x256
        fused_level_kernel<256, 256><<<grid, 256>>>(g1, g2, out + off1);
    }
    {
        dim3 grid(128 / 64, 128 / 32, NIMG);  // coarse 128x128
        fused_level_kernel<128, 128><<<grid, 256>>>(g2, g3, out + off2);
    }
    {
        dim3 grid(64 / 64, 64 / 32, NIMG);    // coarse 64x64; g4 = lpyr[4]
        fused_level_kernel<64, 64><<<grid, 256>>>(g3, out + off4, out + off3);
    }
}

// round 3
// speedup vs baseline: 1.3111x; 1.3111x over previous
#include <cuda_runtime.h>

// Laplacian pyramid, 5 levels, (16,3,1024,1024) fp32, edge-clamp padding.
// Per level, one fused kernel: reduce (5x5 binomial, stride 2) + laplacian
// (fine - expand(coarse)). Register-staged: each thread produces 4 coarse
// pixels from vectorized fine loads and keeps the matching 2x8 fine block in
// registers; SMEM holds only the coarse tile + 1-halo for the expand exchange.

#define NIMG 48  // 16 * 3

__device__ float g_g1[NIMG * 512 * 512];
__device__ float g_g2[NIMG * 256 * 256];
__device__ float g_g3[NIMG * 128 * 128];

template <int Hc, int Wc>
__global__ __launch_bounds__(256) void fused_level_kernel(
    const float* __restrict__ fine,
    float* __restrict__ coarse_out,
    float* __restrict__ lap_out)
{
    constexpr int H = 2 * Hc, W = 2 * Wc;
    constexpr int TCY = 16, TCX = 64;          // coarse tile per CTA
    __shared__ float sc[TCY + 2][TCX + 4];     // coarse + 1-halo, padded

    const int gx = threadIdx.x;                // 0..15 (4 coarse cols each)
    const int iy = threadIdx.y;                // 0..15 (1 coarse row)
    const int tid = iy * 16 + gx;
    const int img = blockIdx.z;
    const int c0y = blockIdx.y * TCY;
    const int c0x = blockIdx.x * TCX;
    const int ci  = c0y + iy;                  // this thread's coarse row
    const int cj0 = c0x + 4 * gx;              // first of 4 coarse cols

    const float* fp = fine + (size_t)img * H * W;

    const bool leftE  = (cj0 == 0);
    const bool rightE = (cj0 == Wc - 4);
    const int cbase = 2 * cj0 - 4;             // 16B-aligned fine col base

    const float hw0 = 0.0625f, hw1 = 0.25f, hw2 = 0.375f;
    const float hwv[5] = {hw0, hw1, hw2, hw1, hw0};

    float acc[4] = {0.f, 0.f, 0.f, 0.f};
    float sf0[8], sf1[8];                      // fine rows 2ci, 2ci+1, cols 2cj0..+7

    // ---- stage 1: reduce — 5 fine rows, 16-float register window each ----
#pragma unroll
    for (int a = 0; a < 5; a++) {
        int r = 2 * ci - 2 + a;
        r = r < 0 ? 0 : (r >= H ? H - 1 : r);
        const float* rp = fp + (size_t)r * W;

        float buf[16];
        if (!leftE) {
            float4 q = *(const float4*)(rp + cbase);
            buf[0] = q.x; buf[1] = q.y; buf[2] = q.z; buf[3] = q.w;
        }
        {
            float4 q = *(const float4*)(rp + cbase + 4);
            buf[4] = q.x; buf[5] = q.y; buf[6] = q.z; buf[7] = q.w;
            float4 p = *(const float4*)(rp + cbase + 8);
            buf[8] = p.x; buf[9] = p.y; buf[10] = p.z; buf[11] = p.w;
        }
        if (!rightE) {
            float4 q = *(const float4*)(rp + cbase + 12);
            buf[12] = q.x; buf[13] = q.y; buf[14] = q.z; buf[15] = q.w;
        } else {
            buf[12] = buf[11];                 // clamp col W -> W-1
        }
        if (leftE) { buf[2] = buf[4]; buf[3] = buf[4]; }  // clamp cols -2,-1 -> 0

        float wa = hwv[a];
#pragma unroll
        for (int t = 0; t < 4; t++) {
            float hv = fmaf(hw0, buf[2 + 2 * t] + buf[6 + 2 * t],
                       fmaf(hw1, buf[3 + 2 * t] + buf[5 + 2 * t],
                            hw2 * buf[4 + 2 * t]));
            acc[t] = fmaf(wa, hv, acc[t]);
        }
        if (a == 2) {
#pragma unroll
            for (int k = 0; k < 8; k++) sf0[k] = buf[4 + k];
        }
        if (a == 3) {
#pragma unroll
            for (int k = 0; k < 8; k++) sf1[k] = buf[4 + k];
        }
    }

    // write coarse (global, vectorized) + stage into SMEM
    {
        float* cop = coarse_out + (size_t)img * Hc * Wc;
        *(float4*)(cop + (size_t)ci * Wc + cj0) =
            make_float4(acc[0], acc[1], acc[2], acc[3]);
#pragma unroll
        for (int t = 0; t < 4; t++) sc[iy + 1][1 + 4 * gx + t] = acc[t];
    }

    // ---- halo ring: 164 positions, clamped scalar fallback ----
    if (tid < 2 * (TCX + 2) + 2 * TCY) {
        int srow, scol;
        if (tid < TCX + 2)            { srow = 0;        scol = tid; }
        else if (tid < 2 * (TCX + 2)) { srow = TCY + 1;  scol = tid - (TCX + 2); }
        else if (tid < 2 * (TCX + 2) + TCY) { srow = tid - 2 * (TCX + 2) + 1; scol = 0; }
        else                          { srow = tid - (2 * (TCX + 2) + TCY) + 1; scol = TCX + 1; }

        int gci = c0y + srow - 1;
        gci = gci < 0 ? 0 : (gci >= Hc ? Hc - 1 : gci);
        int gcj = c0x + scol - 1;
        gcj = gcj < 0 ? 0 : (gcj >= Wc ? Wc - 1 : gcj);

        float a2 = 0.f;
#pragma unroll
        for (int a = 0; a < 5; a++) {
            int r = 2 * gci - 2 + a;
            r = r < 0 ? 0 : (r >= H ? H - 1 : r);
            const float* rp = fp + (size_t)r * W;
            float rs = 0.f;
#pragma unroll
            for (int b = 0; b < 5; b++) {
                int x = 2 * gcj - 2 + b;
                x = x < 0 ? 0 : (x >= W ? W - 1 : x);
                rs = fmaf(hwv[b], rp[x], rs);
            }
            a2 = fmaf(hwv[a], rs, a2);
        }
        sc[srow][scol] = a2;
    }

    __syncthreads();

    // ---- stage 2: laplacian from SMEM coarse + register fine ----
    {
        float c[3][6];
#pragma unroll
        for (int r = 0; r < 3; r++)
#pragma unroll
            for (int k = 0; k < 6; k++)
                c[r][k] = sc[iy + r][4 * gx + k];

        float rowE[6], rowO[6];
#pragma unroll
        for (int k = 0; k < 6; k++) {
            rowE[k] = fmaf(0.75f, c[1][k], 0.125f * (c[0][k] + c[2][k]));
            rowO[k] = 0.5f * (c[1][k] + c[2][k]);
        }

        float oE[8], oO[8];                    // fine cols 2cj0..2cj0+7
#pragma unroll
        for (int t = 0; t < 4; t++) {
            oE[2 * t]     = fmaf(0.75f, rowE[t + 1], 0.125f * (rowE[t] + rowE[t + 2]));
            oE[2 * t + 1] = 0.5f * (rowE[t + 1] + rowE[t + 2]);
            oO[2 * t]     = fmaf(0.75f, rowO[t + 1], 0.125f * (rowO[t] + rowO[t + 2]));
            oO[2 * t + 1] = 0.5f * (rowO[t + 1] + rowO[t + 2]);
        }

        float* lop = lap_out + (size_t)img * H * W;
        size_t top = (size_t)(2 * ci) * W + 2 * cj0;
        size_t bot = top + W;
        *(float4*)(lop + top)     = make_float4(sf0[0] - oE[0], sf0[1] - oE[1],
                                                sf0[2] - oE[2], sf0[3] - oE[3]);
        *(float4*)(lop + top + 4) = make_float4(sf0[4] - oE[4], sf0[5] - oE[5],
                                                sf0[6] - oE[6], sf0[7] - oE[7]);
        *(float4*)(lop + bot)     = make_float4(sf1[0] - oO[0], sf1[1] - oO[1],
                                                sf1[2] - oO[2], sf1[3] - oO[3]);
        *(float4*)(lop + bot + 4) = make_float4(sf1[4] - oO[4], sf1[5] - oO[5],
                                                sf1[6] - oO[6], sf1[7] - oO[7]);
    }
}

extern "C" void kernel_launch(void* const* d_in, const int* in_sizes, int n_in,
                              void* d_out, int out_size) {
    const float* im = (const float*)d_in[0];
    float* out = (float*)d_out;

    float* g1; float* g2; float* g3;
    cudaGetSymbolAddress((void**)&g1, g_g1);
    cudaGetSymbolAddress((void**)&g2, g_g2);
    cudaGetSymbolAddress((void**)&g3, g_g3);

    const long long off0 = 0;
    const long long off1 = off0 + (long long)NIMG * 1024 * 1024;
    const long long off2 = off1 + (long long)NIMG * 512 * 512;
    const long long off3 = off2 + (long long)NIMG * 256 * 256;
    const long long off4 = off3 + (long long)NIMG * 128 * 128;

    dim3 block(16, 16);

    // level l: fine = g_l, writes g_{l+1} and lap_l
    {
        dim3 grid(512 / 64, 512 / 16, NIMG);   // coarse 512x512
        fused_level_kernel<512, 512><<<grid, block>>>(im, g1, out + off0);
    }
    {
        dim3 grid(256 / 64, 256 / 16, NIMG);   // coarse 256x256
        fused_level_kernel<256, 256><<<grid, block>>>(g1, g2, out + off1);
    }
    {
        dim3 grid(128 / 64, 128 / 16, NIMG);   // coarse 128x128
        fused_level_kernel<128, 128><<<grid, block>>>(g2, g3, out + off2);
    }
    {
        dim3 grid(64 / 64, 64 / 16, NIMG);     // coarse 64x64; g4 = lpyr[4]
        fused_level_kernel<64, 64><<<grid, block>>>(g3, out + off4, out + off3);
    }
}

// round 4
// speedup vs baseline: 1.3668x; 1.0425x over previous
#include <cuda_runtime.h>

// Laplacian pyramid, 5 levels, (16,3,1024,1024) fp32, edge-clamp padding.
// Fused per level: reduce (5x5 binomial, stride 2) + laplacian
// (fine - expand(coarse)). Each thread produces a 2x4 coarse block from 7
// fine-row register windows (rows shared between the two coarse rows) and
// keeps the matching 4x8 fine block in registers for the laplacian. SMEM
// holds only the coarse tile + 1-halo for the 3x3 expand exchange.

#define NIMG 48  // 16 * 3

__device__ float g_g1[NIMG * 512 * 512];
__device__ float g_g2[NIMG * 256 * 256];
__device__ float g_g3[NIMG * 128 * 128];

template <int Hc, int Wc>
__global__ __launch_bounds__(256) void fused_level_kernel(
    const float* __restrict__ fine,
    float* __restrict__ coarse_out,
    float* __restrict__ lap_out)
{
    constexpr int H = 2 * Hc, W = 2 * Wc;
    constexpr int TCY = 32, TCX = 64;          // coarse tile per CTA
    __shared__ float sc[TCY + 2][TCX + 4];     // coarse + 1-halo, padded

    const int gx = threadIdx.x;                // 0..15 (4 coarse cols)
    const int iy = threadIdx.y;                // 0..15 (2 coarse rows)
    const int tid = iy * 16 + gx;
    const int img = blockIdx.z;
    const int c0y = blockIdx.y * TCY;
    const int c0x = blockIdx.x * TCX;
    const int ci0 = c0y + 2 * iy;              // first of 2 coarse rows
    const int cj0 = c0x + 4 * gx;              // first of 4 coarse cols

    const float* fp = fine + (size_t)img * H * W;

    const bool leftE  = (cj0 == 0);
    const bool rightE = (cj0 == Wc - 4);
    const int cbase = 2 * cj0 - 4;             // 16B-aligned fine col base

    const float hw0 = 0.0625f, hw1 = 0.25f, hw2 = 0.375f;
    const float hwv[5] = {hw0, hw1, hw2, hw1, hw0};

    float acc0[4] = {0.f, 0.f, 0.f, 0.f};      // coarse row ci0
    float acc1[4] = {0.f, 0.f, 0.f, 0.f};      // coarse row ci0+1
    float sfr[4][8];                           // fine rows 2ci0..2ci0+3, cols 2cj0..+7

    // ---- stage 1: reduce — 7 fine rows cover both coarse rows ----
#pragma unroll
    for (int a = 0; a < 7; a++) {
        int r = 2 * ci0 - 2 + a;
        r = r < 0 ? 0 : (r >= H ? H - 1 : r);
        const float* rp = fp + (size_t)r * W;

        float buf[16];
        if (!leftE) {
            float4 q = *(const float4*)(rp + cbase);
            buf[0] = q.x; buf[1] = q.y; buf[2] = q.z; buf[3] = q.w;
        }
        {
            float4 q = *(const float4*)(rp + cbase + 4);
            buf[4] = q.x; buf[5] = q.y; buf[6] = q.z; buf[7] = q.w;
            float4 p = *(const float4*)(rp + cbase + 8);
            buf[8] = p.x; buf[9] = p.y; buf[10] = p.z; buf[11] = p.w;
        }
        if (!rightE) {
            float4 q = *(const float4*)(rp + cbase + 12);
            buf[12] = q.x; buf[13] = q.y; buf[14] = q.z; buf[15] = q.w;
        } else {
            buf[12] = buf[11];                 // clamp col W -> W-1
        }
        if (leftE) { buf[2] = buf[4]; buf[3] = buf[4]; }  // clamp cols -2,-1 -> 0

        float hv[4];
#pragma unroll
        for (int t = 0; t < 4; t++) {
            hv[t] = fmaf(hw0, buf[2 + 2 * t] + buf[6 + 2 * t],
                    fmaf(hw1, buf[3 + 2 * t] + buf[5 + 2 * t],
                         hw2 * buf[4 + 2 * t]));
        }
        if (a < 5) {
            float w = hwv[a];
#pragma unroll
            for (int t = 0; t < 4; t++) acc0[t] = fmaf(w, hv[t], acc0[t]);
        }
        if (a >= 2) {
            float w = hwv[a - 2];
#pragma unroll
            for (int t = 0; t < 4; t++) acc1[t] = fmaf(w, hv[t], acc1[t]);
        }
        if (a >= 2 && a < 6) {
#pragma unroll
            for (int k = 0; k < 8; k++) sfr[a - 2][k] = buf[4 + k];
        }
    }

    // write coarse (global, vectorized) + stage into SMEM
    {
        float* cop = coarse_out + (size_t)img * Hc * Wc;
        *(float4*)(cop + (size_t)ci0 * Wc + cj0) =
            make_float4(acc0[0], acc0[1], acc0[2], acc0[3]);
        *(float4*)(cop + (size_t)(ci0 + 1) * Wc + cj0) =
            make_float4(acc1[0], acc1[1], acc1[2], acc1[3]);
#pragma unroll
        for (int t = 0; t < 4; t++) {
            sc[2 * iy + 1][1 + 4 * gx + t] = acc0[t];
            sc[2 * iy + 2][1 + 4 * gx + t] = acc1[t];
        }
    }

    // ---- halo ring: 2*(TCX+2) + 2*TCY = 196 positions, clamped fallback ----
    if (tid < 2 * (TCX + 2) + 2 * TCY) {
        int srow, scol;
        if (tid < TCX + 2)            { srow = 0;        scol = tid; }
        else if (tid < 2 * (TCX + 2)) { srow = TCY + 1;  scol = tid - (TCX + 2); }
        else if (tid < 2 * (TCX + 2) + TCY) { srow = tid - 2 * (TCX + 2) + 1; scol = 0; }
        else                          { srow = tid - (2 * (TCX + 2) + TCY) + 1; scol = TCX + 1; }

        int gci = c0y + srow - 1;
        gci = gci < 0 ? 0 : (gci >= Hc ? Hc - 1 : gci);
        int gcj = c0x + scol - 1;
        gcj = gcj < 0 ? 0 : (gcj >= Wc ? Wc - 1 : gcj);

        float a2 = 0.f;
#pragma unroll
        for (int a = 0; a < 5; a++) {
            int r = 2 * gci - 2 + a;
            r = r < 0 ? 0 : (r >= H ? H - 1 : r);
            const float* rp = fp + (size_t)r * W;
            float rs = 0.f;
#pragma unroll
            for (int b = 0; b < 5; b++) {
                int x = 2 * gcj - 2 + b;
                x = x < 0 ? 0 : (x >= W ? W - 1 : x);
                rs = fmaf(hwv[b], rp[x], rs);
            }
            a2 = fmaf(hwv[a], rs, a2);
        }
        sc[srow][scol] = a2;
    }

    __syncthreads();

    // ---- stage 2: laplacian from SMEM coarse + register fine ----
    {
        float c4[4][6];
#pragma unroll
        for (int r = 0; r < 4; r++)
#pragma unroll
            for (int k = 0; k < 6; k++)
                c4[r][k] = sc[2 * iy + r][4 * gx + k];

        float* lop = lap_out + (size_t)img * H * W;

#pragma unroll
        for (int p = 0; p < 2; p++) {          // coarse row ci0 + p
            float rowE[6], rowO[6];
#pragma unroll
            for (int k = 0; k < 6; k++) {
                rowE[k] = fmaf(0.75f, c4[p + 1][k], 0.125f * (c4[p][k] + c4[p + 2][k]));
                rowO[k] = 0.5f * (c4[p + 1][k] + c4[p + 2][k]);
            }
            float oE[8], oO[8];
#pragma unroll
            for (int t = 0; t < 4; t++) {
                oE[2 * t]     = fmaf(0.75f, rowE[t + 1], 0.125f * (rowE[t] + rowE[t + 2]));
                oE[2 * t + 1] = 0.5f * (rowE[t + 1] + rowE[t + 2]);
                oO[2 * t]     = fmaf(0.75f, rowO[t + 1], 0.125f * (rowO[t] + rowO[t + 2]));
                oO[2 * t + 1] = 0.5f * (rowO[t + 1] + rowO[t + 2]);
            }

            const float* fE = sfr[2 * p];      // fine row 2*(ci0+p)
            const float* fO = sfr[2 * p + 1];  // fine row 2*(ci0+p)+1
            size_t top = (size_t)(2 * (ci0 + p)) * W + 2 * cj0;
            size_t bot = top + W;

            __stcs((float4*)(lop + top),
                   make_float4(fE[0] - oE[0], fE[1] - oE[1], fE[2] - oE[2], fE[3] - oE[3]));
            __stcs((float4*)(lop + top + 4),
                   make_float4(fE[4] - oE[4], fE[5] - oE[5], fE[6] - oE[6], fE[7] - oE[7]));
            __stcs((float4*)(lop + bot),
                   make_float4(fO[0] - oO[0], fO[1] - oO[1], fO[2] - oO[2], fO[3] - oO[3]));
            __stcs((float4*)(lop + bot + 4),
                   make_float4(fO[4] - oO[4], fO[5] - oO[5], fO[6] - oO[6], fO[7] - oO[7]));
        }
    }
}

extern "C" void kernel_launch(void* const* d_in, const int* in_sizes, int n_in,
                              void* d_out, int out_size) {
    const float* im = (const float*)d_in[0];
    float* out = (float*)d_out;

    float* g1; float* g2; float* g3;
    cudaGetSymbolAddress((void**)&g1, g_g1);
    cudaGetSymbolAddress((void**)&g2, g_g2);
    cudaGetSymbolAddress((void**)&g3, g_g3);

    const long long off0 = 0;
    const long long off1 = off0 + (long long)NIMG * 1024 * 1024;
    const long long off2 = off1 + (long long)NIMG * 512 * 512;
    const long long off3 = off2 + (long long)NIMG * 256 * 256;
    const long long off4 = off3 + (long long)NIMG * 128 * 128;

    dim3 block(16, 16);

    // level l: fine = g_l, writes g_{l+1} and lap_l
    {
        dim3 grid(512 / 64, 512 / 32, NIMG);   // coarse 512x512
        fused_level_kernel<512, 512><<<grid, block>>>(im, g1, out + off0);
    }
    {
        dim3 grid(256 / 64, 256 / 32, NIMG);   // coarse 256x256
        fused_level_kernel<256, 256><<<grid, block>>>(g1, g2, out + off1);
    }
    {
        dim3 grid(128 / 64, 128 / 32, NIMG);   // coarse 128x128
        fused_level_kernel<128, 128><<<grid, block>>>(g2, g3, out + off2);
    }
    {
        dim3 grid(64 / 64, 64 / 32, NIMG);     // coarse 64x64; g4 = lpyr[4]
        fused_level_kernel<64, 64><<<grid, block>>>(g3, out + off4, out + off3);
    }
}